// round 1
// baseline (speedup 1.0000x reference)
#include <cuda_runtime.h>
#include <math.h>

#define B_   2
#define S_   2048
#define D_   1024
#define H_   16
#define DK_  64
#define NROWS (B_ * S_)   // 4096

// Scratch (allocation-free rule: __device__ globals)
__device__ float g_Q[NROWS * D_];
__device__ float g_K[NROWS * D_];
__device__ float g_V[NROWS * D_];
__device__ float g_A[NROWS * D_];

// ---------------------------------------------------------------------------
// C[M, Nd] = A[M, K] @ W[Nd, K]^T + bias[Nd]
// 128x128 block, BK=8, 256 threads, 8x8 micro-tile per thread.
// ---------------------------------------------------------------------------
__global__ void __launch_bounds__(256) gemm_bias_kernel(
    const float* __restrict__ A, const float* __restrict__ W,
    const float* __restrict__ bias, float* __restrict__ C,
    int M, int Nd, int K)
{
    const int BK = 8;
    __shared__ float As[8][128];
    __shared__ float Ws[8][128];

    int tid = threadIdx.x;
    int tx = tid & 15;        // 0..15  -> 8 output cols each
    int ty = tid >> 4;        // 0..15  -> 8 output rows each
    int m0 = blockIdx.y * 128;
    int n0 = blockIdx.x * 128;

    int lr = tid >> 1;        // 0..127 : tile row to load
    int lc = (tid & 1) * 4;   // 0 or 4 : k-offset (float4)

    const float* Ap = A + (size_t)(m0 + lr) * K + lc;
    const float* Wp = W + (size_t)(n0 + lr) * K + lc;

    float acc[8][8];
    #pragma unroll
    for (int i = 0; i < 8; i++)
        #pragma unroll
        for (int j = 0; j < 8; j++) acc[i][j] = 0.f;

    for (int k0 = 0; k0 < K; k0 += BK) {
        float4 av = *(const float4*)(Ap + k0);
        float4 wv = *(const float4*)(Wp + k0);
        As[lc + 0][lr] = av.x; As[lc + 1][lr] = av.y;
        As[lc + 2][lr] = av.z; As[lc + 3][lr] = av.w;
        Ws[lc + 0][lr] = wv.x; Ws[lc + 1][lr] = wv.y;
        Ws[lc + 2][lr] = wv.z; Ws[lc + 3][lr] = wv.w;
        __syncthreads();

        #pragma unroll
        for (int k = 0; k < BK; k++) {
            float a[8], bb[8];
            *(float4*)&a[0]  = *(const float4*)&As[k][ty * 8];
            *(float4*)&a[4]  = *(const float4*)&As[k][ty * 8 + 4];
            *(float4*)&bb[0] = *(const float4*)&Ws[k][tx * 8];
            *(float4*)&bb[4] = *(const float4*)&Ws[k][tx * 8 + 4];
            #pragma unroll
            for (int i = 0; i < 8; i++)
                #pragma unroll
                for (int j = 0; j < 8; j++)
                    acc[i][j] = fmaf(a[i], bb[j], acc[i][j]);
        }
        __syncthreads();
    }

    #pragma unroll
    for (int i = 0; i < 8; i++) {
        int m = m0 + ty * 8 + i;
        #pragma unroll
        for (int j = 0; j < 8; j++) {
            int n = n0 + tx * 8 + j;
            C[(size_t)m * Nd + n] = acc[i][j] + bias[n];
        }
    }
}

// ---------------------------------------------------------------------------
// Flash-attention fp32. One block = one (b,h) x 64-row Q tile.
// 256 threads: ty = tid/16 owns 4 q-rows, tx = tid%16 owns 4 kv-cols / 4 d-cols.
// Online softmax with shuffle reductions over the 16-lane row group.
// ---------------------------------------------------------------------------
__global__ void __launch_bounds__(256) attn_kernel(
    const float* __restrict__ Q, const float* __restrict__ K,
    const float* __restrict__ V, const int* __restrict__ mask,
    float* __restrict__ O)
{
    const int PITCH = 65;   // 64 + 1 pad: 4*65 = 260 ≡ 4 (mod 32) -> ≤2-way conflicts
    extern __shared__ float sm[];
    float* Qs = sm;
    float* Ks = Qs + 64 * PITCH;
    float* Vs = Ks + 64 * PITCH;
    float* Ps = Vs + 64 * PITCH;

    int bh = blockIdx.y;
    int b = bh >> 4;
    int h = bh & 15;
    int q0 = blockIdx.x * 64;
    int tid = threadIdx.x;
    int tx = tid & 15;
    int ty = tid >> 4;

    // Load Q tile (64 rows x DK cols), head slice of [B,S,D] layout
    const float* Qb = Q + ((size_t)(b * S_ + q0)) * D_ + h * DK_;
    for (int i = tid; i < 64 * 64; i += 256) {
        int r = i >> 6, c = i & 63;
        Qs[r * PITCH + c] = Qb[(size_t)r * D_ + c];
    }

    float m_i[4], l_i[4], acc[4][4];
    #pragma unroll
    for (int i = 0; i < 4; i++) {
        m_i[i] = -INFINITY;
        l_i[i] = 0.f;
        #pragma unroll
        for (int j = 0; j < 4; j++) acc[i][j] = 0.f;
    }

    const int* mb = mask + (size_t)b * S_ * S_;

    for (int kt = 0; kt < S_; kt += 64) {
        __syncthreads();   // protect Ks/Vs/Ps from previous iteration readers
        const float* Kb = K + ((size_t)(b * S_ + kt)) * D_ + h * DK_;
        const float* Vb = V + ((size_t)(b * S_ + kt)) * D_ + h * DK_;
        for (int i = tid; i < 64 * 64; i += 256) {
            int r = i >> 6, c = i & 63;
            Ks[r * PITCH + c] = Kb[(size_t)r * D_ + c];
            Vs[r * PITCH + c] = Vb[(size_t)r * D_ + c];
        }
        __syncthreads();

        // S = Q K^T for this 64x64 tile (4x4 per thread)
        float s[4][4];
        #pragma unroll
        for (int i = 0; i < 4; i++)
            #pragma unroll
            for (int j = 0; j < 4; j++) s[i][j] = 0.f;

        #pragma unroll 8
        for (int k = 0; k < DK_; k++) {
            float a[4], bq[4];
            #pragma unroll
            for (int i = 0; i < 4; i++) a[i] = Qs[(ty * 4 + i) * PITCH + k];
            #pragma unroll
            for (int j = 0; j < 4; j++) bq[j] = Ks[(tx * 4 + j) * PITCH + k];
            #pragma unroll
            for (int i = 0; i < 4; i++)
                #pragma unroll
                for (int j = 0; j < 4; j++)
                    s[i][j] = fmaf(a[i], bq[j], s[i][j]);
        }

        // Scale + mask + online softmax (per owned row)
        #pragma unroll
        for (int i = 0; i < 4; i++) {
            int r = ty * 4 + i;
            const int* mrow = mb + (size_t)(q0 + r) * S_ + kt;
            float tmax = -INFINITY;
            #pragma unroll
            for (int j = 0; j < 4; j++) {
                int c = tx * 4 + j;
                s[i][j] = mrow[c] ? s[i][j] * 0.125f : -1e9f;
                tmax = fmaxf(tmax, s[i][j]);
            }
            #pragma unroll
            for (int off = 8; off; off >>= 1)
                tmax = fmaxf(tmax, __shfl_xor_sync(0xffffffffu, tmax, off));

            float mnew  = fmaxf(m_i[i], tmax);
            float alpha = __expf(m_i[i] - mnew);
            float rsum  = 0.f;
            #pragma unroll
            for (int j = 0; j < 4; j++) {
                float p = __expf(s[i][j] - mnew);
                Ps[r * PITCH + tx * 4 + j] = p;
                rsum += p;
            }
            #pragma unroll
            for (int off = 8; off; off >>= 1)
                rsum += __shfl_xor_sync(0xffffffffu, rsum, off);

            l_i[i] = l_i[i] * alpha + rsum;
            m_i[i] = mnew;
            #pragma unroll
            for (int j = 0; j < 4; j++) acc[i][j] *= alpha;
        }
        __syncthreads();

        // O += P @ V  (4x4 per thread over the 64-deep kv dimension)
        #pragma unroll 8
        for (int k = 0; k < 64; k++) {
            float pv[4], vv[4];
            #pragma unroll
            for (int i = 0; i < 4; i++) pv[i] = Ps[(ty * 4 + i) * PITCH + k];
            #pragma unroll
            for (int j = 0; j < 4; j++) vv[j] = Vs[k * PITCH + tx * 4 + j];
            #pragma unroll
            for (int i = 0; i < 4; i++)
                #pragma unroll
                for (int j = 0; j < 4; j++)
                    acc[i][j] = fmaf(pv[i], vv[j], acc[i][j]);
        }
    }

    // Write normalized output back in [B,S,D] layout (heads re-merged)
    #pragma unroll
    for (int i = 0; i < 4; i++) {
        int r = q0 + ty * 4 + i;
        float inv = 1.f / l_i[i];
        #pragma unroll
        for (int j = 0; j < 4; j++)
            O[((size_t)(b * S_ + r)) * D_ + h * DK_ + tx * 4 + j] = acc[i][j] * inv;
    }
}

// ---------------------------------------------------------------------------
extern "C" void kernel_launch(void* const* d_in, const int* in_sizes, int n_in,
                              void* d_out, int out_size)
{
    const float* q    = (const float*)d_in[0];
    const float* k    = (const float*)d_in[1];
    const float* v    = (const float*)d_in[2];
    const int*   mask = (const int*)  d_in[3];
    const float* w_q  = (const float*)d_in[4];
    const float* b_q  = (const float*)d_in[5];
    const float* w_k  = (const float*)d_in[6];
    const float* b_k  = (const float*)d_in[7];
    const float* w_v  = (const float*)d_in[8];
    const float* b_v  = (const float*)d_in[9];
    const float* w_o  = (const float*)d_in[10];
    const float* b_o  = (const float*)d_in[11];
    float* out = (float*)d_out;

    float *Qp, *Kp, *Vp, *Ap;
    cudaGetSymbolAddress((void**)&Qp, g_Q);
    cudaGetSymbolAddress((void**)&Kp, g_K);
    cudaGetSymbolAddress((void**)&Vp, g_V);
    cudaGetSymbolAddress((void**)&Ap, g_A);

    dim3 gemm_grid(D_ / 128, NROWS / 128);

    gemm_bias_kernel<<<gemm_grid, 256>>>(q, w_q, b_q, Qp, NROWS, D_, D_);
    gemm_bias_kernel<<<gemm_grid, 256>>>(k, w_k, b_k, Kp, NROWS, D_, D_);
    gemm_bias_kernel<<<gemm_grid, 256>>>(v, w_v, b_v, Vp, NROWS, D_, D_);

    size_t smem = 4 * 64 * 65 * sizeof(float);   // 66560 B
    cudaFuncSetAttribute(attn_kernel,
                         cudaFuncAttributeMaxDynamicSharedMemorySize, (int)smem);
    attn_kernel<<<dim3(S_ / 64, B_ * H_), 256, smem>>>(Qp, Kp, Vp, mask, Ap);

    gemm_bias_kernel<<<gemm_grid, 256>>>(Ap, w_o, b_o, out, NROWS, D_, D_);
}

// round 2
// speedup vs baseline: 3.1815x; 3.1815x over previous
#include <cuda_runtime.h>
#include <cstdint>
#include <math.h>

#define B_   2
#define S_   2048
#define D_   1024
#define H_   16
#define DK_  64
#define NROWS (B_ * S_)   // 4096

// Scratch (allocation-free rule: __device__ globals)
__device__ float g_Q[NROWS * D_];
__device__ float g_K[NROWS * D_];
__device__ float g_V[NROWS * D_];
__device__ float g_A[NROWS * D_];

// ---------------------------------------------------------------------------
// helpers
// ---------------------------------------------------------------------------
__device__ __forceinline__ uint32_t f2tf(float f) {
    uint32_t u;
    asm("cvt.rna.tf32.f32 %0, %1;" : "=r"(u) : "f"(f));
    return u;
}

__device__ __forceinline__ void mma_m16n8k8(float* c, const uint32_t* a,
                                            uint32_t b0, uint32_t b1) {
    asm volatile(
        "mma.sync.aligned.m16n8k8.row.col.f32.tf32.tf32.f32 "
        "{%0,%1,%2,%3}, {%4,%5,%6,%7}, {%8,%9}, {%0,%1,%2,%3};\n"
        : "+f"(c[0]), "+f"(c[1]), "+f"(c[2]), "+f"(c[3])
        : "r"(a[0]), "r"(a[1]), "r"(a[2]), "r"(a[3]), "r"(b0), "r"(b1));
}

__device__ __forceinline__ void cp16(void* sdst, const void* gsrc) {
    uint32_t s = (uint32_t)__cvta_generic_to_shared(sdst);
    asm volatile("cp.async.ca.shared.global [%0], [%1], 16;\n" :: "r"(s), "l"(gsrc));
}

// ---------------------------------------------------------------------------
// C[M, Nd] = A[M, K] @ W[Nd, K]^T + bias  — tf32 mma, cp.async double buffer
// Block 128x128, K-stage 32, 256 threads; warps 2(m) x 4(n), warp tile 64x32.
// ---------------------------------------------------------------------------
#define GP 36   // smem pitch (floats): (36*r + c) % 32 == (4r + c) % 32 -> conflict-free frags
__global__ void __launch_bounds__(256) gemm_tf32(
    const float* __restrict__ A, const float* __restrict__ W,
    const float* __restrict__ bias, float* __restrict__ C,
    int M, int Nd, int K)
{
    extern __shared__ float sm[];
    float* As = sm;                 // 2 * 128 * 36
    float* Bs = sm + 2 * 128 * GP;  // 2 * 128 * 36

    const int tid  = threadIdx.x;
    const int lane = tid & 31, wid = tid >> 5;
    const int g = lane >> 2, t = lane & 3;
    const int wm = (wid >> 2) * 64;
    const int wn = (wid & 3) * 32;
    const int m0 = blockIdx.y * 128, n0 = blockIdx.x * 128;

    const int k4 = (tid & 7) << 2;  // 0,4,...,28
    const int rb = tid >> 3;        // 0..31

    float acc[4][4][4];
    #pragma unroll
    for (int i = 0; i < 4; i++)
        #pragma unroll
        for (int j = 0; j < 4; j++)
            #pragma unroll
            for (int q = 0; q < 4; q++) acc[i][j][q] = 0.f;

    // prologue: stage 0
    {
        float* Ad = As; float* Bd = Bs;
        #pragma unroll
        for (int j = 0; j < 4; j++) {
            int r = rb + 32 * j;
            cp16(Ad + r * GP + k4, A + (size_t)(m0 + r) * K + k4);
            cp16(Bd + r * GP + k4, W + (size_t)(n0 + r) * K + k4);
        }
        asm volatile("cp.async.commit_group;\n");
    }

    const int NS = K / 32;
    for (int s = 0; s < NS; s++) {
        asm volatile("cp.async.wait_group 0;\n");
        __syncthreads();
        if (s + 1 < NS) {
            int kt = (s + 1) * 32;
            float* Ad = As + ((s + 1) & 1) * 128 * GP;
            float* Bd = Bs + ((s + 1) & 1) * 128 * GP;
            #pragma unroll
            for (int j = 0; j < 4; j++) {
                int r = rb + 32 * j;
                cp16(Ad + r * GP + k4, A + (size_t)(m0 + r) * K + kt + k4);
                cp16(Bd + r * GP + k4, W + (size_t)(n0 + r) * K + kt + k4);
            }
            asm volatile("cp.async.commit_group;\n");
        }
        const float* Ab = As + (s & 1) * 128 * GP;
        const float* Bb = Bs + (s & 1) * 128 * GP;

        #pragma unroll
        for (int ks = 0; ks < 4; ks++) {
            uint32_t af[4][4], bf[4][2];
            #pragma unroll
            for (int mt = 0; mt < 4; mt++) {
                int r = wm + mt * 16;
                af[mt][0] = f2tf(Ab[(r + g)     * GP + ks * 8 + t]);
                af[mt][1] = f2tf(Ab[(r + g + 8) * GP + ks * 8 + t]);
                af[mt][2] = f2tf(Ab[(r + g)     * GP + ks * 8 + t + 4]);
                af[mt][3] = f2tf(Ab[(r + g + 8) * GP + ks * 8 + t + 4]);
            }
            #pragma unroll
            for (int nt = 0; nt < 4; nt++) {
                int c = wn + nt * 8;
                bf[nt][0] = f2tf(Bb[(c + g) * GP + ks * 8 + t]);
                bf[nt][1] = f2tf(Bb[(c + g) * GP + ks * 8 + t + 4]);
            }
            #pragma unroll
            for (int mt = 0; mt < 4; mt++)
                #pragma unroll
                for (int nt = 0; nt < 4; nt++)
                    mma_m16n8k8(acc[mt][nt], af[mt], bf[nt][0], bf[nt][1]);
        }
    }

    // epilogue
    #pragma unroll
    for (int mt = 0; mt < 4; mt++) {
        int r0 = m0 + wm + mt * 16 + g;
        #pragma unroll
        for (int nt = 0; nt < 4; nt++) {
            int c = n0 + wn + nt * 8 + 2 * t;
            float2 bv = *(const float2*)(bias + c);
            float2 o0 = make_float2(acc[mt][nt][0] + bv.x, acc[mt][nt][1] + bv.y);
            float2 o1 = make_float2(acc[mt][nt][2] + bv.x, acc[mt][nt][3] + bv.y);
            *(float2*)(C + (size_t)r0 * Nd + c)       = o0;
            *(float2*)(C + (size_t)(r0 + 8) * Nd + c) = o1;
        }
    }
}

// ---------------------------------------------------------------------------
// Flash attention, tf32 mma. Block = 128 q-rows x one (b,h). 8 warps; each
// warp owns 16 q-rows (softmax stats stay inside the warp: 4-lane shuffles).
// Q fragments in registers for all 32 KV tiles. Bc = 64.
// smem pitches chosen so fragment reads are bank-conflict-free.
// ---------------------------------------------------------------------------
__global__ void __launch_bounds__(256) attn_tf32(
    const float* __restrict__ Qg, const float* __restrict__ Kg,
    const float* __restrict__ Vg, const int* __restrict__ mask,
    float* __restrict__ O)
{
    extern __shared__ float sm[];
    float* Ps = sm;                   // 128*68 floats (Q staging, then P)
    float* Ks = sm + 128 * 68;        // 64*68
    float* Vs = Ks + 64 * 68;         // 64*72
    unsigned char* Ms = (unsigned char*)(Vs + 64 * 72);  // 128*68 bytes

    const int tid  = threadIdx.x;
    const int lane = tid & 31, wid = tid >> 5;
    const int g = lane >> 2, t = lane & 3;
    const int w16 = wid * 16;
    const int bh = blockIdx.y, b = bh >> 4, h = bh & 15;
    const int q0 = blockIdx.x * 128;

    // stage Q tile [128 x 64] into Ps, then extract fragments to registers
    const float* Qb = Qg + ((size_t)(b * S_ + q0)) * D_ + h * DK_;
    for (int i = tid; i < 128 * 16; i += 256) {
        int r = i >> 4, c4 = (i & 15) << 2;
        float4 v = *(const float4*)(Qb + (size_t)r * D_ + c4);
        float* d = Ps + r * 68 + c4;
        d[0] = v.x; d[1] = v.y; d[2] = v.z; d[3] = v.w;
    }
    __syncthreads();
    uint32_t qf[8][4];
    #pragma unroll
    for (int ks = 0; ks < 8; ks++) {
        qf[ks][0] = f2tf(Ps[(w16 + g)     * 68 + ks * 8 + t]);
        qf[ks][1] = f2tf(Ps[(w16 + g + 8) * 68 + ks * 8 + t]);
        qf[ks][2] = f2tf(Ps[(w16 + g)     * 68 + ks * 8 + t + 4]);
        qf[ks][3] = f2tf(Ps[(w16 + g + 8) * 68 + ks * 8 + t + 4]);
    }

    float oacc[8][4];
    #pragma unroll
    for (int i = 0; i < 8; i++)
        #pragma unroll
        for (int j = 0; j < 4; j++) oacc[i][j] = 0.f;
    float mr0 = -INFINITY, mr1 = -INFINITY, lr0 = 0.f, lr1 = 0.f;

    const int* mb = mask + (size_t)b * S_ * S_ + (size_t)q0 * S_;

    for (int kt = 0; kt < S_; kt += 64) {
        __syncthreads();   // Ks/Vs/Ms free from previous iteration
        const float* Kb = Kg + ((size_t)(b * S_ + kt)) * D_ + h * DK_;
        const float* Vb = Vg + ((size_t)(b * S_ + kt)) * D_ + h * DK_;
        for (int i = tid; i < 64 * 16; i += 256) {
            int r = i >> 4, c4 = (i & 15) << 2;
            float4 kv = *(const float4*)(Kb + (size_t)r * D_ + c4);
            float* kd = Ks + r * 68 + c4;
            kd[0] = __uint_as_float(f2tf(kv.x)); kd[1] = __uint_as_float(f2tf(kv.y));
            kd[2] = __uint_as_float(f2tf(kv.z)); kd[3] = __uint_as_float(f2tf(kv.w));
            float4 vv = *(const float4*)(Vb + (size_t)r * D_ + c4);
            float* vd = Vs + r * 72 + c4;
            vd[0] = __uint_as_float(f2tf(vv.x)); vd[1] = __uint_as_float(f2tf(vv.y));
            vd[2] = __uint_as_float(f2tf(vv.z)); vd[3] = __uint_as_float(f2tf(vv.w));
        }
        for (int i = tid; i < 128 * 16; i += 256) {   // mask 128x64 ints
            int r = i >> 4, c4 = (i & 15) << 2;
            int4 mv = *(const int4*)(mb + (size_t)r * S_ + kt + c4);
            *(uchar4*)(Ms + r * 68 + c4) = make_uchar4(
                (unsigned char)(mv.x != 0), (unsigned char)(mv.y != 0),
                (unsigned char)(mv.z != 0), (unsigned char)(mv.w != 0));
        }
        __syncthreads();

        // S = Q K^T  (warp rows x 64 kv cols)
        float sacc[8][4];
        #pragma unroll
        for (int i = 0; i < 8; i++)
            #pragma unroll
            for (int j = 0; j < 4; j++) sacc[i][j] = 0.f;
        #pragma unroll
        for (int nt = 0; nt < 8; nt++) {
            #pragma unroll
            for (int ks = 0; ks < 8; ks++) {
                uint32_t b0 = __float_as_uint(Ks[(nt * 8 + g) * 68 + ks * 8 + t]);
                uint32_t b1 = __float_as_uint(Ks[(nt * 8 + g) * 68 + ks * 8 + t + 4]);
                mma_m16n8k8(sacc[nt], qf[ks], b0, b1);
            }
        }

        // scale + mask + row max
        const float scl = 0.125f;
        float rm0 = -INFINITY, rm1 = -INFINITY;
        #pragma unroll
        for (int nt = 0; nt < 8; nt++) {
            int c = nt * 8 + 2 * t;
            unsigned char k00 = Ms[(w16 + g)     * 68 + c];
            unsigned char k01 = Ms[(w16 + g)     * 68 + c + 1];
            unsigned char k10 = Ms[(w16 + g + 8) * 68 + c];
            unsigned char k11 = Ms[(w16 + g + 8) * 68 + c + 1];
            sacc[nt][0] = k00 ? sacc[nt][0] * scl : -1e9f;
            sacc[nt][1] = k01 ? sacc[nt][1] * scl : -1e9f;
            sacc[nt][2] = k10 ? sacc[nt][2] * scl : -1e9f;
            sacc[nt][3] = k11 ? sacc[nt][3] * scl : -1e9f;
            rm0 = fmaxf(rm0, fmaxf(sacc[nt][0], sacc[nt][1]));
            rm1 = fmaxf(rm1, fmaxf(sacc[nt][2], sacc[nt][3]));
        }
        rm0 = fmaxf(rm0, __shfl_xor_sync(0xffffffffu, rm0, 1));
        rm0 = fmaxf(rm0, __shfl_xor_sync(0xffffffffu, rm0, 2));
        rm1 = fmaxf(rm1, __shfl_xor_sync(0xffffffffu, rm1, 1));
        rm1 = fmaxf(rm1, __shfl_xor_sync(0xffffffffu, rm1, 2));

        float mn0 = fmaxf(mr0, rm0), mn1 = fmaxf(mr1, rm1);
        float a0 = __expf(mr0 - mn0), a1 = __expf(mr1 - mn1);
        float rs0 = 0.f, rs1 = 0.f;
        #pragma unroll
        for (int nt = 0; nt < 8; nt++) {
            float p0 = __expf(sacc[nt][0] - mn0);
            float p1 = __expf(sacc[nt][1] - mn0);
            float p2 = __expf(sacc[nt][2] - mn1);
            float p3 = __expf(sacc[nt][3] - mn1);
            rs0 += p0 + p1; rs1 += p2 + p3;
            int c = nt * 8 + 2 * t;
            Ps[(w16 + g)     * 68 + c]     = __uint_as_float(f2tf(p0));
            Ps[(w16 + g)     * 68 + c + 1] = __uint_as_float(f2tf(p1));
            Ps[(w16 + g + 8) * 68 + c]     = __uint_as_float(f2tf(p2));
            Ps[(w16 + g + 8) * 68 + c + 1] = __uint_as_float(f2tf(p3));
        }
        rs0 += __shfl_xor_sync(0xffffffffu, rs0, 1);
        rs0 += __shfl_xor_sync(0xffffffffu, rs0, 2);
        rs1 += __shfl_xor_sync(0xffffffffu, rs1, 1);
        rs1 += __shfl_xor_sync(0xffffffffu, rs1, 2);
        lr0 = lr0 * a0 + rs0; lr1 = lr1 * a1 + rs1;
        mr0 = mn0; mr1 = mn1;
        #pragma unroll
        for (int nt = 0; nt < 8; nt++) {
            oacc[nt][0] *= a0; oacc[nt][1] *= a0;
            oacc[nt][2] *= a1; oacc[nt][3] *= a1;
        }
        __syncwarp();   // P stores visible to fragment loads across lanes

        // O += P @ V
        #pragma unroll
        for (int ks = 0; ks < 8; ks++) {
            uint32_t pa[4];
            pa[0] = __float_as_uint(Ps[(w16 + g)     * 68 + ks * 8 + t]);
            pa[1] = __float_as_uint(Ps[(w16 + g + 8) * 68 + ks * 8 + t]);
            pa[2] = __float_as_uint(Ps[(w16 + g)     * 68 + ks * 8 + t + 4]);
            pa[3] = __float_as_uint(Ps[(w16 + g + 8) * 68 + ks * 8 + t + 4]);
            #pragma unroll
            for (int nt = 0; nt < 8; nt++) {
                uint32_t b0 = __float_as_uint(Vs[(ks * 8 + t)     * 72 + nt * 8 + g]);
                uint32_t b1 = __float_as_uint(Vs[(ks * 8 + t + 4) * 72 + nt * 8 + g]);
                mma_m16n8k8(oacc[nt], pa, b0, b1);
            }
        }
    }

    // write normalized output, heads re-merged
    float i0 = 1.f / lr0, i1 = 1.f / lr1;
    #pragma unroll
    for (int nt = 0; nt < 8; nt++) {
        int c = h * DK_ + nt * 8 + 2 * t;
        size_t r0 = (size_t)(b * S_ + q0 + w16 + g) * D_ + c;
        size_t r1 = (size_t)(b * S_ + q0 + w16 + g + 8) * D_ + c;
        O[r0] = oacc[nt][0] * i0; O[r0 + 1] = oacc[nt][1] * i0;
        O[r1] = oacc[nt][2] * i1; O[r1 + 1] = oacc[nt][3] * i1;
    }
}

// ---------------------------------------------------------------------------
extern "C" void kernel_launch(void* const* d_in, const int* in_sizes, int n_in,
                              void* d_out, int out_size)
{
    const float* q    = (const float*)d_in[0];
    const float* k    = (const float*)d_in[1];
    const float* v    = (const float*)d_in[2];
    const int*   mask = (const int*)  d_in[3];
    const float* w_q  = (const float*)d_in[4];
    const float* b_q  = (const float*)d_in[5];
    const float* w_k  = (const float*)d_in[6];
    const float* b_k  = (const float*)d_in[7];
    const float* w_v  = (const float*)d_in[8];
    const float* b_v  = (const float*)d_in[9];
    const float* w_o  = (const float*)d_in[10];
    const float* b_o  = (const float*)d_in[11];
    float* out = (float*)d_out;

    float *Qp, *Kp, *Vp, *Ap;
    cudaGetSymbolAddress((void**)&Qp, g_Q);
    cudaGetSymbolAddress((void**)&Kp, g_K);
    cudaGetSymbolAddress((void**)&Vp, g_V);
    cudaGetSymbolAddress((void**)&Ap, g_A);

    const int gemm_smem = 2 * 2 * 128 * GP * sizeof(float);   // 73728
    const int attn_smem = (128 * 68 + 64 * 68 + 64 * 72) * sizeof(float) + 128 * 68;  // 79360

    static bool attr_done = false;
    if (!attr_done) {
        cudaFuncSetAttribute(gemm_tf32,
            cudaFuncAttributeMaxDynamicSharedMemorySize, gemm_smem);
        cudaFuncSetAttribute(attn_tf32,
            cudaFuncAttributeMaxDynamicSharedMemorySize, attn_smem);
        attr_done = true;
    }

    dim3 gemm_grid(D_ / 128, NROWS / 128);   // (8, 32)
    gemm_tf32<<<gemm_grid, 256, gemm_smem>>>(q, w_q, b_q, Qp, NROWS, D_, D_);
    gemm_tf32<<<gemm_grid, 256, gemm_smem>>>(k, w_k, b_k, Kp, NROWS, D_, D_);
    gemm_tf32<<<gemm_grid, 256, gemm_smem>>>(v, w_v, b_v, Vp, NROWS, D_, D_);

    attn_tf32<<<dim3(S_ / 128, B_ * H_), 256, attn_smem>>>(Qp, Kp, Vp, mask, Ap);

    gemm_tf32<<<gemm_grid, 256, gemm_smem>>>(Ap, w_o, b_o, out, NROWS, D_, D_);
}